// round 3
// baseline (speedup 1.0000x reference)
#include <cuda_runtime.h>
#include <cstdint>

#define NN 50000
#define EE 800000
#define DD 128
#define TM 64          // nodes per block in the MLP kernel

// Scratch (allocation-free rule: __device__ globals)
__device__ __align__(16) float g_summed[NN * DD];   // 25.6 MB, L2-resident
__device__ __align__(16) float g_cnt[NN];

// ---------------------------------------------------------------------------
// Kernel 1: zero the accumulators
// ---------------------------------------------------------------------------
__global__ void zero_kernel() {
    const int stride = gridDim.x * blockDim.x;
    int i = blockIdx.x * blockDim.x + threadIdx.x;
    float4 z = make_float4(0.f, 0.f, 0.f, 0.f);
    const int tot4 = NN * DD / 4;
    float4* s4 = reinterpret_cast<float4*>(g_summed);
    for (int idx = i; idx < tot4; idx += stride) s4[idx] = z;
    for (int idx = i; idx < NN; idx += stride) g_cnt[idx] = 0.f;
}

// ---------------------------------------------------------------------------
// Kernel 2: warp-per-edge gather + message + scatter-add
// msg = relu(hidden[src] + edge_attr[e]*We + be), atomicAdd into g_summed[dst]
// edge_index is int32 (JAX default config downcasts int64 arrays).
// ---------------------------------------------------------------------------
__global__ __launch_bounds__(256) void scatter_kernel(
    const float* __restrict__ hidden,
    const int* __restrict__ ei,         // [2, E] int32
    const float* __restrict__ ea,       // [E, 1]
    const float* __restrict__ We,       // [1, D]
    const float* __restrict__ be)       // [D]
{
    int gid = blockIdx.x * blockDim.x + threadIdx.x;
    int e = gid >> 5;
    if (e >= EE) return;
    int lane = threadIdx.x & 31;

    int src = __ldg(&ei[e]);
    int dst = __ldg(&ei[EE + e]);
    float a = __ldg(&ea[e]);

    const float4* h4 = reinterpret_cast<const float4*>(hidden + (size_t)src * DD);
    float4 h = __ldg(&h4[lane]);
    float4 w = __ldg(&reinterpret_cast<const float4*>(We)[lane]);
    float4 b = __ldg(&reinterpret_cast<const float4*>(be)[lane]);

    float4 m;
    m.x = fmaxf(h.x + fmaf(a, w.x, b.x), 0.f);
    m.y = fmaxf(h.y + fmaf(a, w.y, b.y), 0.f);
    m.z = fmaxf(h.z + fmaf(a, w.z, b.z), 0.f);
    m.w = fmaxf(h.w + fmaf(a, w.w, b.w), 0.f);

    float* p = &g_summed[(size_t)dst * DD + lane * 4];
    atomicAdd(p + 0, m.x);
    atomicAdd(p + 1, m.y);
    atomicAdd(p + 2, m.z);
    atomicAdd(p + 3, m.w);
    if (lane == 0) atomicAdd(&g_cnt[dst], 1.0f);
}

// ---------------------------------------------------------------------------
// Kernel 3: fused aggr-combine + MLP (Linear->ReLU->Linear), 64 nodes/block
// Register tile per thread: 8 rows x 4 cols.  smem buffer reused h0 -> h1.
// ---------------------------------------------------------------------------
__global__ __launch_bounds__(256) void mlp_kernel(
    const float* __restrict__ hidden,
    const float* __restrict__ W1, const float* __restrict__ b1,
    const float* __restrict__ W2, const float* __restrict__ b2,
    const float* __restrict__ eps,
    float* __restrict__ out)
{
    __shared__ float sh[TM * DD];   // 32 KB

    const int base = blockIdx.x * TM;
    const float epsv = 1.0f + __ldg(eps);

    // ---- Stage A: h0 = (1+eps)*hidden + summed/max(cnt,1) --------------------
    {
        const float4* h4 = reinterpret_cast<const float4*>(hidden);
        const float4* s4 = reinterpret_cast<const float4*>(g_summed);
        float4* sh4 = reinterpret_cast<float4*>(sh);
        for (int i = threadIdx.x; i < TM * DD / 4; i += 256) {
            int row = i >> 5;            // 32 float4 per row
            int col = i & 31;
            int n = base + row;
            float4 v = make_float4(0.f, 0.f, 0.f, 0.f);
            if (n < NN) {
                float4 hv = __ldg(&h4[(size_t)n * 32 + col]);
                float4 sv = s4[(size_t)n * 32 + col];
                float inv = 1.0f / fmaxf(g_cnt[n], 1.0f);
                v.x = fmaf(epsv, hv.x, sv.x * inv);
                v.y = fmaf(epsv, hv.y, sv.y * inv);
                v.z = fmaf(epsv, hv.z, sv.z * inv);
                v.w = fmaf(epsv, hv.w, sv.w * inv);
            }
            sh4[i] = v;
        }
    }
    __syncthreads();

    const int c = threadIdx.x & 31;   // output col group: cols 4c..4c+3
    const int r = threadIdx.x >> 5;   // row group: rows 8r..8r+7

    float acc[8][4];

    // ---- Stage B: h1 = relu(h0 @ W1 + b1) -----------------------------------
    #pragma unroll
    for (int rr = 0; rr < 8; rr++)
        #pragma unroll
        for (int j = 0; j < 4; j++) acc[rr][j] = 0.f;

    {
        const float4* W1v = reinterpret_cast<const float4*>(W1);
        #pragma unroll 4
        for (int k = 0; k < DD; k += 4) {
            float4 w0 = __ldg(&W1v[(k + 0) * 32 + c]);
            float4 w1 = __ldg(&W1v[(k + 1) * 32 + c]);
            float4 w2 = __ldg(&W1v[(k + 2) * 32 + c]);
            float4 w3 = __ldg(&W1v[(k + 3) * 32 + c]);
            #pragma unroll
            for (int rr = 0; rr < 8; rr++) {
                float4 h = *reinterpret_cast<const float4*>(&sh[(r * 8 + rr) * DD + k]);
                acc[rr][0] = fmaf(h.x, w0.x, fmaf(h.y, w1.x, fmaf(h.z, w2.x, fmaf(h.w, w3.x, acc[rr][0]))));
                acc[rr][1] = fmaf(h.x, w0.y, fmaf(h.y, w1.y, fmaf(h.z, w2.y, fmaf(h.w, w3.y, acc[rr][1]))));
                acc[rr][2] = fmaf(h.x, w0.z, fmaf(h.y, w1.z, fmaf(h.z, w2.z, fmaf(h.w, w3.z, acc[rr][2]))));
                acc[rr][3] = fmaf(h.x, w0.w, fmaf(h.y, w1.w, fmaf(h.z, w2.w, fmaf(h.w, w3.w, acc[rr][3]))));
            }
        }
    }
    __syncthreads();   // all reads of h0 done

    {
        float4 bb = __ldg(&reinterpret_cast<const float4*>(b1)[c]);
        #pragma unroll
        for (int rr = 0; rr < 8; rr++) {
            float4 o;
            o.x = fmaxf(acc[rr][0] + bb.x, 0.f);
            o.y = fmaxf(acc[rr][1] + bb.y, 0.f);
            o.z = fmaxf(acc[rr][2] + bb.z, 0.f);
            o.w = fmaxf(acc[rr][3] + bb.w, 0.f);
            *reinterpret_cast<float4*>(&sh[(r * 8 + rr) * DD + 4 * c]) = o;
            acc[rr][0] = acc[rr][1] = acc[rr][2] = acc[rr][3] = 0.f;
        }
    }
    __syncthreads();   // h1 visible

    // ---- Stage C: out = h1 @ W2 + b2 ----------------------------------------
    {
        const float4* W2v = reinterpret_cast<const float4*>(W2);
        #pragma unroll 4
        for (int k = 0; k < DD; k += 4) {
            float4 w0 = __ldg(&W2v[(k + 0) * 32 + c]);
            float4 w1 = __ldg(&W2v[(k + 1) * 32 + c]);
            float4 w2 = __ldg(&W2v[(k + 2) * 32 + c]);
            float4 w3 = __ldg(&W2v[(k + 3) * 32 + c]);
            #pragma unroll
            for (int rr = 0; rr < 8; rr++) {
                float4 h = *reinterpret_cast<const float4*>(&sh[(r * 8 + rr) * DD + k]);
                acc[rr][0] = fmaf(h.x, w0.x, fmaf(h.y, w1.x, fmaf(h.z, w2.x, fmaf(h.w, w3.x, acc[rr][0]))));
                acc[rr][1] = fmaf(h.x, w0.y, fmaf(h.y, w1.y, fmaf(h.z, w2.y, fmaf(h.w, w3.y, acc[rr][1]))));
                acc[rr][2] = fmaf(h.x, w0.z, fmaf(h.y, w1.z, fmaf(h.z, w2.z, fmaf(h.w, w3.z, acc[rr][2]))));
                acc[rr][3] = fmaf(h.x, w0.w, fmaf(h.y, w1.w, fmaf(h.z, w2.w, fmaf(h.w, w3.w, acc[rr][3]))));
            }
        }
    }

    {
        float4 bb = __ldg(&reinterpret_cast<const float4*>(b2)[c]);
        #pragma unroll
        for (int rr = 0; rr < 8; rr++) {
            int n = base + r * 8 + rr;
            if (n < NN) {
                float4 o;
                o.x = acc[rr][0] + bb.x;
                o.y = acc[rr][1] + bb.y;
                o.z = acc[rr][2] + bb.z;
                o.w = acc[rr][3] + bb.w;
                reinterpret_cast<float4*>(out)[(size_t)n * 32 + c] = o;
            }
        }
    }
}

// ---------------------------------------------------------------------------
extern "C" void kernel_launch(void* const* d_in, const int* in_sizes, int n_in,
                              void* d_out, int out_size) {
    const float* hidden = (const float*)d_in[0];
    const int*   ei     = (const int*)d_in[1];     // int32 [2, E]
    const float* ea     = (const float*)d_in[2];
    const float* We     = (const float*)d_in[3];
    const float* be     = (const float*)d_in[4];
    const float* W1     = (const float*)d_in[5];
    const float* b1     = (const float*)d_in[6];
    const float* W2     = (const float*)d_in[7];
    const float* b2     = (const float*)d_in[8];
    const float* eps    = (const float*)d_in[9];
    float* out = (float*)d_out;

    zero_kernel<<<1024, 256>>>();

    int scatter_blocks = (EE * 32 + 255) / 256;   // warp per edge
    scatter_kernel<<<scatter_blocks, 256>>>(hidden, ei, ea, We, be);

    int mlp_blocks = (NN + TM - 1) / TM;
    mlp_kernel<<<mlp_blocks, 256>>>(hidden, W1, b1, W2, b2, eps, out);
}

// round 5
// speedup vs baseline: 1.4575x; 1.4575x over previous
#include <cuda_runtime.h>
#include <cstdint>

#define NN 50000
#define EE 800000
#define DD 128
#define TM 64          // nodes per block in the fused MLP kernel

// Scratch (allocation-free rule: __device__ globals) — ~9.8 MB total
__device__ int   g_deg[NN];
__device__ int   g_cursor[NN];     // seeded with g_off by scan_kernel
__device__ int   g_off[NN + 1];
__device__ int   g_src[EE];
__device__ __align__(8) float g_a[EE];

// ---------------------------------------------------------------------------
// Kernel 1: zero degree
// ---------------------------------------------------------------------------
__global__ void zero_kernel() {
    int i = blockIdx.x * blockDim.x + threadIdx.x;
    if (i < NN) g_deg[i] = 0;
}

// ---------------------------------------------------------------------------
// Kernel 2: degree histogram over dst
// ---------------------------------------------------------------------------
__global__ __launch_bounds__(256) void hist_kernel(const int* __restrict__ ei) {
    int e = blockIdx.x * blockDim.x + threadIdx.x;
    if (e >= EE) return;
    atomicAdd(&g_deg[__ldg(&ei[EE + e])], 1);
}

// ---------------------------------------------------------------------------
// Kernel 3: exclusive scan of g_deg -> g_off (and seed g_cursor)
// single block, 1024 threads, warp-shuffle scan + cross-warp combine
// ---------------------------------------------------------------------------
__global__ __launch_bounds__(1024) void scan_kernel() {
    __shared__ int wsum[32];
    __shared__ int carry_sh;
    const int lane = threadIdx.x & 31;
    const int wid  = threadIdx.x >> 5;
    if (threadIdx.x == 0) carry_sh = 0;
    __syncthreads();

    for (int base = 0; base < NN; base += 1024) {
        int i = base + threadIdx.x;
        int v = (i < NN) ? g_deg[i] : 0;
        int orig = v;
        // warp inclusive scan
        #pragma unroll
        for (int off = 1; off < 32; off <<= 1) {
            int t = __shfl_up_sync(0xffffffffu, v, off);
            if (lane >= off) v += t;
        }
        if (lane == 31) wsum[wid] = v;
        __syncthreads();
        if (wid == 0) {
            int s = wsum[lane];
            #pragma unroll
            for (int off = 1; off < 32; off <<= 1) {
                int t = __shfl_up_sync(0xffffffffu, s, off);
                if (lane >= off) s += t;
            }
            wsum[lane] = s;
        }
        __syncthreads();
        int warp_prefix = (wid > 0) ? wsum[wid - 1] : 0;
        int carry = carry_sh;
        if (i < NN) {
            int excl = carry + warp_prefix + v - orig;
            g_off[i] = excl;
            g_cursor[i] = excl;
        }
        __syncthreads();
        if (threadIdx.x == 1023) carry_sh = carry + wsum[31];
        __syncthreads();
    }
    if (threadIdx.x == 0) g_off[NN] = carry_sh;   // == EE
}

// ---------------------------------------------------------------------------
// Kernel 4: fill CSR buckets (src index + edge_attr per slot)
// ---------------------------------------------------------------------------
__global__ __launch_bounds__(256) void fill_kernel(
    const int* __restrict__ ei, const float* __restrict__ ea)
{
    int e = blockIdx.x * blockDim.x + threadIdx.x;
    if (e >= EE) return;
    int src = __ldg(&ei[e]);
    int dst = __ldg(&ei[EE + e]);
    int slot = atomicAdd(&g_cursor[dst], 1);
    g_src[slot] = src;
    g_a[slot]   = __ldg(&ea[e]);
}

// ---------------------------------------------------------------------------
// Kernel 5: fused CSR-aggregate + (1+eps)*h + mean + MLP (L->ReLU->L)
// 64 nodes/block, 256 threads.  Warp-per-node register aggregation.
// Register tile per thread in GEMMs: 8 rows x 4 cols.
// ---------------------------------------------------------------------------
__global__ __launch_bounds__(256) void fused_kernel(
    const float* __restrict__ hidden,
    const float* __restrict__ We, const float* __restrict__ be,
    const float* __restrict__ W1, const float* __restrict__ b1,
    const float* __restrict__ W2, const float* __restrict__ b2,
    const float* __restrict__ eps,
    float* __restrict__ out)
{
    __shared__ float sh[TM * DD];   // 32 KB, reused h0 -> h1

    const int base = blockIdx.x * TM;
    const float epsv = 1.0f + __ldg(eps);
    const int lane = threadIdx.x & 31;
    const int wid  = threadIdx.x >> 5;   // 8 warps

    // ---- Stage A: aggregate in registers, warp-per-node (8 nodes per warp) --
    {
        const float4* h4 = reinterpret_cast<const float4*>(hidden);
        float4 w = __ldg(&reinterpret_cast<const float4*>(We)[lane]);
        float4 b = __ldg(&reinterpret_cast<const float4*>(be)[lane]);
        float4* sh4 = reinterpret_cast<float4*>(sh);

        #pragma unroll 1
        for (int j = 0; j < 8; j++) {
            int row = wid * 8 + j;
            int n = base + row;
            float4 v = make_float4(0.f, 0.f, 0.f, 0.f);
            if (n < NN) {
                int s0 = __ldg(&g_off[n]);
                int s1 = __ldg(&g_off[n + 1]);
                float4 acc = make_float4(0.f, 0.f, 0.f, 0.f);
                #pragma unroll 2
                for (int s = s0; s < s1; s++) {
                    int   src = __ldg(&g_src[s]);
                    float a   = __ldg(&g_a[s]);
                    float4 h = __ldg(&h4[(size_t)src * 32 + lane]);
                    acc.x += fmaxf(h.x + fmaf(a, w.x, b.x), 0.f);
                    acc.y += fmaxf(h.y + fmaf(a, w.y, b.y), 0.f);
                    acc.z += fmaxf(h.z + fmaf(a, w.z, b.z), 0.f);
                    acc.w += fmaxf(h.w + fmaf(a, w.w, b.w), 0.f);
                }
                float inv = 1.0f / fmaxf((float)(s1 - s0), 1.0f);
                float4 hv = __ldg(&h4[(size_t)n * 32 + lane]);
                v.x = fmaf(epsv, hv.x, acc.x * inv);
                v.y = fmaf(epsv, hv.y, acc.y * inv);
                v.z = fmaf(epsv, hv.z, acc.z * inv);
                v.w = fmaf(epsv, hv.w, acc.w * inv);
            }
            sh4[row * 32 + lane] = v;
        }
    }
    __syncthreads();

    const int c = lane;               // output col group: cols 4c..4c+3
    const int r = wid;                // row group: rows 8r..8r+7

    float acc[8][4];

    // ---- Stage B: h1 = relu(h0 @ W1 + b1) -----------------------------------
    #pragma unroll
    for (int rr = 0; rr < 8; rr++)
        #pragma unroll
        for (int j = 0; j < 4; j++) acc[rr][j] = 0.f;

    {
        const float4* W1v = reinterpret_cast<const float4*>(W1);
        #pragma unroll 4
        for (int k = 0; k < DD; k += 4) {
            float4 w0 = __ldg(&W1v[(k + 0) * 32 + c]);
            float4 w1 = __ldg(&W1v[(k + 1) * 32 + c]);
            float4 w2 = __ldg(&W1v[(k + 2) * 32 + c]);
            float4 w3 = __ldg(&W1v[(k + 3) * 32 + c]);
            #pragma unroll
            for (int rr = 0; rr < 8; rr++) {
                float4 h = *reinterpret_cast<const float4*>(&sh[(r * 8 + rr) * DD + k]);
                acc[rr][0] = fmaf(h.x, w0.x, fmaf(h.y, w1.x, fmaf(h.z, w2.x, fmaf(h.w, w3.x, acc[rr][0]))));
                acc[rr][1] = fmaf(h.x, w0.y, fmaf(h.y, w1.y, fmaf(h.z, w2.y, fmaf(h.w, w3.y, acc[rr][1]))));
                acc[rr][2] = fmaf(h.x, w0.z, fmaf(h.y, w1.z, fmaf(h.z, w2.z, fmaf(h.w, w3.z, acc[rr][2]))));
                acc[rr][3] = fmaf(h.x, w0.w, fmaf(h.y, w1.w, fmaf(h.z, w2.w, fmaf(h.w, w3.w, acc[rr][3]))));
            }
        }
    }
    __syncthreads();   // all reads of h0 done

    {
        float4 bb = __ldg(&reinterpret_cast<const float4*>(b1)[c]);
        #pragma unroll
        for (int rr = 0; rr < 8; rr++) {
            float4 o;
            o.x = fmaxf(acc[rr][0] + bb.x, 0.f);
            o.y = fmaxf(acc[rr][1] + bb.y, 0.f);
            o.z = fmaxf(acc[rr][2] + bb.z, 0.f);
            o.w = fmaxf(acc[rr][3] + bb.w, 0.f);
            *reinterpret_cast<float4*>(&sh[(r * 8 + rr) * DD + 4 * c]) = o;
            acc[rr][0] = acc[rr][1] = acc[rr][2] = acc[rr][3] = 0.f;
        }
    }
    __syncthreads();   // h1 visible

    // ---- Stage C: out = h1 @ W2 + b2 ----------------------------------------
    {
        const float4* W2v = reinterpret_cast<const float4*>(W2);
        #pragma unroll 4
        for (int k = 0; k < DD; k += 4) {
            float4 w0 = __ldg(&W2v[(k + 0) * 32 + c]);
            float4 w1 = __ldg(&W2v[(k + 1) * 32 + c]);
            float4 w2 = __ldg(&W2v[(k + 2) * 32 + c]);
            float4 w3 = __ldg(&W2v[(k + 3) * 32 + c]);
            #pragma unroll
            for (int rr = 0; rr < 8; rr++) {
                float4 h = *reinterpret_cast<const float4*>(&sh[(r * 8 + rr) * DD + k]);
                acc[rr][0] = fmaf(h.x, w0.x, fmaf(h.y, w1.x, fmaf(h.z, w2.x, fmaf(h.w, w3.x, acc[rr][0]))));
                acc[rr][1] = fmaf(h.x, w0.y, fmaf(h.y, w1.y, fmaf(h.z, w2.y, fmaf(h.w, w3.y, acc[rr][1]))));
                acc[rr][2] = fmaf(h.x, w0.z, fmaf(h.y, w1.z, fmaf(h.z, w2.z, fmaf(h.w, w3.z, acc[rr][2]))));
                acc[rr][3] = fmaf(h.x, w0.w, fmaf(h.y, w1.w, fmaf(h.z, w2.w, fmaf(h.w, w3.w, acc[rr][3]))));
            }
        }
    }

    {
        float4 bb = __ldg(&reinterpret_cast<const float4*>(b2)[c]);
        #pragma unroll
        for (int rr = 0; rr < 8; rr++) {
            int n = base + r * 8 + rr;
            if (n < NN) {
                float4 o;
                o.x = acc[rr][0] + bb.x;
                o.y = acc[rr][1] + bb.y;
                o.z = acc[rr][2] + bb.z;
                o.w = acc[rr][3] + bb.w;
                reinterpret_cast<float4*>(out)[(size_t)n * 32 + c] = o;
            }
        }
    }
}

// ---------------------------------------------------------------------------
extern "C" void kernel_launch(void* const* d_in, const int* in_sizes, int n_in,
                              void* d_out, int out_size) {
    const float* hidden = (const float*)d_in[0];
    const int*   ei     = (const int*)d_in[1];     // int32 [2, E]
    const float* ea     = (const float*)d_in[2];
    const float* We     = (const float*)d_in[3];
    const float* be     = (const float*)d_in[4];
    const float* W1     = (const float*)d_in[5];
    const float* b1     = (const float*)d_in[6];
    const float* W2     = (const float*)d_in[7];
    const float* b2     = (const float*)d_in[8];
    const float* eps    = (const float*)d_in[9];
    float* out = (float*)d_out;

    zero_kernel<<<(NN + 255) / 256, 256>>>();
    hist_kernel<<<(EE + 255) / 256, 256>>>(ei);
    scan_kernel<<<1, 1024>>>();
    fill_kernel<<<(EE + 255) / 256, 256>>>(ei, ea);

    int mlp_blocks = (NN + TM - 1) / TM;
    fused_kernel<<<mlp_blocks, 256>>>(hidden, We, be, W1, b1, W2, b2, eps, out);
}